// round 3
// baseline (speedup 1.0000x reference)
#include <cuda_runtime.h>
#include <cuda_bf16.h>
#include <cstdint>

// ---------------- problem constants ----------------
#define D_MODEL 1024
#define N_HEADS 16
#define D_HEAD  64
#define LATENT  32
#define T_SEQ   4096
#define NEG_INF (-1e9f)

// ---------------- device scratch (no allocs allowed) ----------------
#define MAX_BT 8192
__device__ float g_lat[MAX_BT * LATENT];
__device__ float g_K  [MAX_BT * D_MODEL];
__device__ float g_V  [MAX_BT * D_MODEL];
__device__ float g_Q  [MAX_BT * D_MODEL];
__device__ float g_O  [MAX_BT * D_MODEL];
__device__ float g_X  [MAX_BT * D_MODEL];          // tf32-rounded x
__device__ float g_Wq [D_MODEL * D_MODEL];         // tf32-rounded W_q
__device__ float g_Wo [D_MODEL * D_MODEL];         // tf32-rounded W_o

// ---------------- helpers ----------------
__device__ __forceinline__ float f2tf(float f) {
    uint32_t u;
    asm("cvt.rna.tf32.f32 %0, %1;" : "=r"(u) : "f"(f));
    return __uint_as_float(u);
}
__device__ __forceinline__ void mma_tf32(float c[4],
                                         uint32_t a0, uint32_t a1, uint32_t a2, uint32_t a3,
                                         uint32_t b0, uint32_t b1) {
    asm volatile(
        "mma.sync.aligned.m16n8k8.row.col.f32.tf32.tf32.f32 "
        "{%0,%1,%2,%3},{%4,%5,%6,%7},{%8,%9},{%0,%1,%2,%3};"
        : "+f"(c[0]), "+f"(c[1]), "+f"(c[2]), "+f"(c[3])
        : "r"(a0), "r"(a1), "r"(a2), "r"(a3), "r"(b0), "r"(b1));
}
__device__ __forceinline__ void cp16(uint32_t s, const void* g) {
    asm volatile("cp.async.cg.shared.global [%0], [%1], 16;" :: "r"(s), "l"(g));
}
__device__ __forceinline__ void cp_commit() {
    asm volatile("cp.async.commit_group;");
}
__device__ __forceinline__ void cp_wait_all() {
    asm volatile("cp.async.wait_group 0;");
}

// =====================================================================
// Kernel 0: elementwise tf32 rounding (float4)
// =====================================================================
__global__ void round_kernel(const float* __restrict__ src,
                             float* __restrict__ dst, int n4) {
    int i = blockIdx.x * blockDim.x + threadIdx.x;
    if (i < n4) {
        float4 v = ((const float4*)src)[i];
        ((float4*)dst)[i] = make_float4(f2tf(v.x), f2tf(v.y), f2tf(v.z), f2tf(v.w));
    }
}

// =====================================================================
// Kernel 1: lat = x @ W_kv  (fp32 exact)
// =====================================================================
__global__ void lat_kernel(const float* __restrict__ x,
                           const float* __restrict__ Wkv,
                           float* __restrict__ lat) {
    int col = threadIdx.x & 31;
    int rg  = threadIdx.x >> 5;
    int row0 = blockIdx.x * 32 + rg * 4;
    float acc0 = 0.f, acc1 = 0.f, acc2 = 0.f, acc3 = 0.f;
    const float* x0 = x + (size_t)row0 * D_MODEL;
    const float* x1 = x0 + D_MODEL;
    const float* x2 = x1 + D_MODEL;
    const float* x3 = x2 + D_MODEL;
#pragma unroll 4
    for (int k = 0; k < D_MODEL; k++) {
        float w = __ldg(Wkv + k * LATENT + col);
        acc0 += x0[k] * w;
        acc1 += x1[k] * w;
        acc2 += x2[k] * w;
        acc3 += x3[k] * w;
    }
    lat[(size_t)(row0 + 0) * LATENT + col] = acc0;
    lat[(size_t)(row0 + 1) * LATENT + col] = acc1;
    lat[(size_t)(row0 + 2) * LATENT + col] = acc2;
    lat[(size_t)(row0 + 3) * LATENT + col] = acc3;
}

// =====================================================================
// Kernel 2: K,V = lat @ W_k / W_v  (fp32 exact, stores tf32-rounded)
// =====================================================================
__global__ void kv_kernel(const float* __restrict__ lat,
                          const float* __restrict__ Wk,
                          const float* __restrict__ Wv,
                          float* __restrict__ K,
                          float* __restrict__ V) {
    __shared__ float ls[4][LATENT];
    int bt0 = blockIdx.x * 4;
    if (threadIdx.x < 4 * LATENT) {
        int r = threadIdx.x / LATENT, l = threadIdx.x % LATENT;
        ls[r][l] = lat[(size_t)(bt0 + r) * LATENT + l];
    }
    __syncthreads();
    int c0 = threadIdx.x * 4;
    float4 ak[4], av[4];
#pragma unroll
    for (int r = 0; r < 4; r++) { ak[r] = make_float4(0,0,0,0); av[r] = make_float4(0,0,0,0); }
#pragma unroll 4
    for (int l = 0; l < LATENT; l++) {
        float4 wk = *(const float4*)(Wk + (size_t)l * D_MODEL + c0);
        float4 wv = *(const float4*)(Wv + (size_t)l * D_MODEL + c0);
#pragma unroll
        for (int r = 0; r < 4; r++) {
            float lv = ls[r][l];
            ak[r].x += lv * wk.x; ak[r].y += lv * wk.y; ak[r].z += lv * wk.z; ak[r].w += lv * wk.w;
            av[r].x += lv * wv.x; av[r].y += lv * wv.y; av[r].z += lv * wv.z; av[r].w += lv * wv.w;
        }
    }
#pragma unroll
    for (int r = 0; r < 4; r++) {
        *(float4*)(K + (size_t)(bt0 + r) * D_MODEL + c0) =
            make_float4(f2tf(ak[r].x), f2tf(ak[r].y), f2tf(ak[r].z), f2tf(ak[r].w));
        *(float4*)(V + (size_t)(bt0 + r) * D_MODEL + c0) =
            make_float4(f2tf(av[r].x), f2tf(av[r].y), f2tf(av[r].z), f2tf(av[r].w));
    }
}

// =====================================================================
// Kernel 3/5: tf32 MMA GEMM, cp.async double-buffered.
// Inputs PRE-ROUNDED to tf32. 128x128 tile, kc=16, 256 thr, warp 64x32.
// =====================================================================
#define GA 36     // A smem row stride (floats)
#define GB 136    // B smem row stride (floats)
#define GA_SZ (128 * GA)
#define GB_SZ (16 * GB)
__global__ __launch_bounds__(256, 2)
void gemm_tf32(const float* __restrict__ A,
               const float* __restrict__ B,
               float* __restrict__ C,
               int M, int N, int K, int round_out) {
    __shared__ float As[2 * GA_SZ];
    __shared__ float Bs[2 * GB_SZ];
    const int tid = threadIdx.x;
    const int lane = tid & 31;
    const int wid = tid >> 5;
    const int bm = blockIdx.y * 128;
    const int bn = blockIdx.x * 128;
    const int wm = (wid >> 2) * 64;
    const int wn = (wid & 3) * 32;
    const int lq = lane >> 2;
    const int lr = lane & 3;

    // loader indices (2 chunks each for A and B)
    const int a_row0 = tid >> 1;            // chunks 0..511: row=idx>>2
    // use idx = tid + i*256: A row = idx>>2, ch = idx&3 ; B row = idx>>5, ch = idx&31
    uint32_t asb = __cvta_generic_to_shared(As);
    uint32_t bsb = __cvta_generic_to_shared(Bs);
    (void)a_row0;

    float acc[4][4][4];
#pragma unroll
    for (int mt = 0; mt < 4; mt++)
#pragma unroll
        for (int nt = 0; nt < 4; nt++)
#pragma unroll
            for (int j = 0; j < 4; j++) acc[mt][nt][j] = 0.f;

    auto issue_stage = [&](int k0, int buf) {
#pragma unroll
        for (int i = 0; i < 2; i++) {
            int idx = tid + i * 256;
            int row = idx >> 2, ch = idx & 3;
            cp16(asb + (uint32_t)(buf * GA_SZ + row * GA + ch * 4) * 4,
                 A + (size_t)(bm + row) * K + k0 + ch * 4);
        }
#pragma unroll
        for (int i = 0; i < 2; i++) {
            int idx = tid + i * 256;
            int row = idx >> 5, ch = idx & 31;
            cp16(bsb + (uint32_t)(buf * GB_SZ + row * GB + ch * 4) * 4,
                 B + (size_t)(k0 + row) * N + bn + ch * 4);
        }
        cp_commit();
    };

    issue_stage(0, 0);

    const int niter = K / 16;
    for (int it = 0; it < niter; it++) {
        cp_wait_all();
        __syncthreads();
        if (it + 1 < niter) issue_stage((it + 1) * 16, (it + 1) & 1);

        const float* Ab = As + (it & 1) * GA_SZ;
        const float* Bb = Bs + (it & 1) * GB_SZ;
#pragma unroll
        for (int kk = 0; kk < 16; kk += 8) {
            uint32_t a[4][4];
#pragma unroll
            for (int mt = 0; mt < 4; mt++) {
                int r = wm + mt * 16 + lq;
                a[mt][0] = __float_as_uint(Ab[r * GA + kk + lr]);
                a[mt][1] = __float_as_uint(Ab[(r + 8) * GA + kk + lr]);
                a[mt][2] = __float_as_uint(Ab[r * GA + kk + lr + 4]);
                a[mt][3] = __float_as_uint(Ab[(r + 8) * GA + kk + lr + 4]);
            }
#pragma unroll
            for (int nt = 0; nt < 4; nt++) {
                uint32_t b0 = __float_as_uint(Bb[(kk + lr) * GB + wn + nt * 8 + lq]);
                uint32_t b1 = __float_as_uint(Bb[(kk + lr + 4) * GB + wn + nt * 8 + lq]);
#pragma unroll
                for (int mt = 0; mt < 4; mt++)
                    mma_tf32(acc[mt][nt], a[mt][0], a[mt][1], a[mt][2], a[mt][3], b0, b1);
            }
        }
        __syncthreads();
    }

#pragma unroll
    for (int mt = 0; mt < 4; mt++) {
        int r0 = bm + wm + mt * 16 + lq;
#pragma unroll
        for (int nt = 0; nt < 4; nt++) {
            int col = bn + wn + nt * 8 + 2 * lr;
            float v0 = acc[mt][nt][0], v1 = acc[mt][nt][1];
            float v2 = acc[mt][nt][2], v3 = acc[mt][nt][3];
            if (round_out) { v0 = f2tf(v0); v1 = f2tf(v1); v2 = f2tf(v2); v3 = f2tf(v3); }
            *(float2*)(C + (size_t)r0 * N + col)       = make_float2(v0, v1);
            *(float2*)(C + (size_t)(r0 + 8) * N + col) = make_float2(v2, v3);
        }
    }
}

// =====================================================================
// Kernel 4: causal flash attention, tf32 MMA, cp.async pipelined.
// 256 thr / 8 warps; q-tile 128 (warp owns 16 rows); k-tile 64.
// Q fragments in registers; K stride 68 / V stride 72 row-major smem
// (conflict-free scalar frag reads); P in fragment-major smem (LDS.128).
// All inputs pre-rounded to tf32.
// =====================================================================
#define KSTR 68
#define VSTR 72
#define KSZ (64 * KSTR)
#define VSZ (64 * VSTR)
#define PGRP 132
#define PWARP (8 * PGRP)       // 1056 floats per warp
#define QSTG_STR 68
// smem floats: K 2 stages + V 2 stages + P/Q-stage region
#define P_REGION (128 * QSTG_STR)   // 8704 >= 8*PWARP (8448)
__global__ __launch_bounds__(256, 2)
void attn_kernel(const float* __restrict__ Q,
                 const float* __restrict__ K,
                 const float* __restrict__ V,
                 float* __restrict__ O,
                 int T) {
    extern __shared__ float sm[];
    float* Kbuf = sm;                       // [2][KSZ]
    float* Vbuf = Kbuf + 2 * KSZ;           // [2][VSZ]
    float* Ps   = Vbuf + 2 * VSZ;           // [P_REGION]

    const int qt  = (gridDim.x - 1) - blockIdx.x;   // heavy tiles first
    const int bh  = blockIdx.y;
    const int b   = bh >> 4;
    const int h   = bh & 15;
    const int tid = threadIdx.x;
    const int wid = tid >> 5;
    const int lane = tid & 31;
    const int lq = lane >> 2;
    const int lr = lane & 3;
    const float scale = 0.125f;

    const size_t base = ((size_t)b * T) * D_MODEL + (size_t)h * D_HEAD;
    const float* Kg = K + base;
    const float* Vg = V + base;

    uint32_t kvs = __cvta_generic_to_shared(Kbuf);
    uint32_t vvs = __cvta_generic_to_shared(Vbuf);

    // issue K/V tile 0 copy
    auto issue_tile = [&](int kt, int buf) {
        const float* kg = Kg + (size_t)(kt * 64) * D_MODEL;
        const float* vg = Vg + (size_t)(kt * 64) * D_MODEL;
#pragma unroll
        for (int i = 0; i < 4; i++) {
            int c = tid + i * 256;            // 0..1023 K chunks
            int row = c >> 4, ch = c & 15;
            cp16(kvs + (uint32_t)(buf * KSZ + row * KSTR + ch * 4) * 4,
                 kg + (size_t)row * D_MODEL + ch * 4);
        }
#pragma unroll
        for (int i = 0; i < 4; i++) {
            int c = tid + i * 256;            // V chunks
            int row = c >> 4, ch = c & 15;
            cp16(vvs + (uint32_t)(buf * VSZ + row * VSTR + ch * 4) * 4,
                 vg + (size_t)row * D_MODEL + ch * 4);
        }
        cp_commit();
    };

    issue_tile(0, 0);

    // ---- Q tile -> staging (P region), then fragments -> registers ----
#pragma unroll
    for (int i = tid; i < 128 * 16; i += 256) {
        int q = i >> 4, c4 = (i & 15) * 4;
        float4 v = *(const float4*)(Q + base + (size_t)(qt * 128 + q) * D_MODEL + c4);
        *(float4*)(&Ps[q * QSTG_STR + c4]) = v;
    }
    __syncthreads();

    uint32_t qa0[8], qa1[8], qa2[8], qa3[8];
    {
        int r0 = wid * 16 + lq;
#pragma unroll
        for (int kk = 0; kk < 8; kk++) {
            qa0[kk] = __float_as_uint(Ps[r0 * QSTG_STR + kk * 8 + lr]);
            qa1[kk] = __float_as_uint(Ps[(r0 + 8) * QSTG_STR + kk * 8 + lr]);
            qa2[kk] = __float_as_uint(Ps[r0 * QSTG_STR + kk * 8 + lr + 4]);
            qa3[kk] = __float_as_uint(Ps[(r0 + 8) * QSTG_STR + kk * 8 + lr + 4]);
        }
    }
    __syncthreads();   // P region now free for P tiles

    float oacc[8][4];
#pragma unroll
    for (int dt = 0; dt < 8; dt++)
#pragma unroll
        for (int j = 0; j < 4; j++) oacc[dt][j] = 0.f;
    float m0 = -1e30f, m1 = -1e30f, l0 = 0.f, l1 = 0.f;

    const int gq0 = qt * 128 + wid * 16 + lq;
    const int gq1 = gq0 + 8;
    const int kt_max = 2 * qt + 1;

    for (int kt = 0; kt <= kt_max; kt++) {
        cp_wait_all();
        __syncthreads();
        if (kt < kt_max) issue_tile(kt + 1, (kt + 1) & 1);

        const float* Kb = Kbuf + (kt & 1) * KSZ;
        const float* Vb = Vbuf + (kt & 1) * VSZ;

        // ---- S = Q K^T ----
        float sacc[8][4];
#pragma unroll
        for (int n = 0; n < 8; n++)
#pragma unroll
            for (int j = 0; j < 4; j++) sacc[n][j] = 0.f;

#pragma unroll
        for (int kk = 0; kk < 8; kk++) {
#pragma unroll
            for (int n = 0; n < 8; n++) {
                uint32_t b0 = __float_as_uint(Kb[(n * 8 + lq) * KSTR + kk * 8 + lr]);
                uint32_t b1 = __float_as_uint(Kb[(n * 8 + lq) * KSTR + kk * 8 + lr + 4]);
                mma_tf32(sacc[n], qa0[kk], qa1[kk], qa2[kk], qa3[kk], b0, b1);
            }
        }

        // ---- scale + causal mask ----
        const bool needmask = (kt >= 2 * qt);
#pragma unroll
        for (int n = 0; n < 8; n++) {
#pragma unroll
            for (int j = 0; j < 4; j++) {
                float v = sacc[n][j] * scale;
                if (needmask) {
                    int gk = kt * 64 + n * 8 + 2 * lr + (j & 1);
                    int gq = (j < 2) ? gq0 : gq1;
                    if (gk > gq) v += NEG_INF;
                }
                sacc[n][j] = v;
            }
        }

        // ---- online softmax ----
        float mx0 = -1e30f, mx1 = -1e30f;
#pragma unroll
        for (int n = 0; n < 8; n++) {
            mx0 = fmaxf(mx0, fmaxf(sacc[n][0], sacc[n][1]));
            mx1 = fmaxf(mx1, fmaxf(sacc[n][2], sacc[n][3]));
        }
        mx0 = fmaxf(mx0, __shfl_xor_sync(0xffffffffu, mx0, 1));
        mx0 = fmaxf(mx0, __shfl_xor_sync(0xffffffffu, mx0, 2));
        mx1 = fmaxf(mx1, __shfl_xor_sync(0xffffffffu, mx1, 1));
        mx1 = fmaxf(mx1, __shfl_xor_sync(0xffffffffu, mx1, 2));
        float mn0 = fmaxf(m0, mx0);
        float mn1 = fmaxf(m1, mx1);
        float c0 = __expf(m0 - mn0);
        float c1 = __expf(m1 - mn1);
        float s0 = 0.f, s1 = 0.f;
#pragma unroll
        for (int n = 0; n < 8; n++) {
            sacc[n][0] = __expf(sacc[n][0] - mn0);
            sacc[n][1] = __expf(sacc[n][1] - mn0);
            sacc[n][2] = __expf(sacc[n][2] - mn1);
            sacc[n][3] = __expf(sacc[n][3] - mn1);
            s0 += sacc[n][0] + sacc[n][1];
            s1 += sacc[n][2] + sacc[n][3];
        }
        s0 += __shfl_xor_sync(0xffffffffu, s0, 1);
        s0 += __shfl_xor_sync(0xffffffffu, s0, 2);
        s1 += __shfl_xor_sync(0xffffffffu, s1, 1);
        s1 += __shfl_xor_sync(0xffffffffu, s1, 2);
        l0 = l0 * c0 + s0;
        l1 = l1 * c1 + s1;
        m0 = mn0; m1 = mn1;
#pragma unroll
        for (int dt = 0; dt < 8; dt++) {
            oacc[dt][0] *= c0; oacc[dt][1] *= c0;
            oacc[dt][2] *= c1; oacc[dt][3] *= c1;
        }

        // ---- P -> fragment-major smem (tf32) ----
        {
            float* Pw = Ps + wid * PWARP;
#pragma unroll
            for (int n = 0; n < 8; n++) {
#pragma unroll
                for (int j = 0; j < 4; j++) {
                    int cfull = 2 * lr + (j & 1);
                    int hc = cfull >> 2, lra = cfull & 3;
                    int hr = j >> 1;
                    int grp = (hr * 2 + hc) * 2 + (n >> 2);
                    Pw[grp * PGRP + (lq * 4 + lra) * 4 + (n & 3)] = f2tf(sacc[n][j]);
                }
            }
        }
        __syncwarp();

        // ---- P fragments (vectorized) ----
        uint32_t pa0[8], pa1[8], pa2[8], pa3[8];
        {
            const float* Pw = Ps + wid * PWARP;
#pragma unroll
            for (int q = 0; q < 2; q++) {
                float4 v00 = *(const float4*)(&Pw[((0 * 2 + 0) * 2 + q) * PGRP + lane * 4]);
                float4 v10 = *(const float4*)(&Pw[((1 * 2 + 0) * 2 + q) * PGRP + lane * 4]);
                float4 v01 = *(const float4*)(&Pw[((0 * 2 + 1) * 2 + q) * PGRP + lane * 4]);
                float4 v11 = *(const float4*)(&Pw[((1 * 2 + 1) * 2 + q) * PGRP + lane * 4]);
                pa0[q*4+0]=__float_as_uint(v00.x); pa0[q*4+1]=__float_as_uint(v00.y);
                pa0[q*4+2]=__float_as_uint(v00.z); pa0[q*4+3]=__float_as_uint(v00.w);
                pa1[q*4+0]=__float_as_uint(v10.x); pa1[q*4+1]=__float_as_uint(v10.y);
                pa1[q*4+2]=__float_as_uint(v10.z); pa1[q*4+3]=__float_as_uint(v10.w);
                pa2[q*4+0]=__float_as_uint(v01.x); pa2[q*4+1]=__float_as_uint(v01.y);
                pa2[q*4+2]=__float_as_uint(v01.z); pa2[q*4+3]=__float_as_uint(v01.w);
                pa3[q*4+0]=__float_as_uint(v11.x); pa3[q*4+1]=__float_as_uint(v11.y);
                pa3[q*4+2]=__float_as_uint(v11.z); pa3[q*4+3]=__float_as_uint(v11.w);
            }
        }

        // ---- O += P V ----
#pragma unroll
        for (int dt = 0; dt < 8; dt++) {
#pragma unroll
            for (int kk = 0; kk < 8; kk++) {
                uint32_t b0 = __float_as_uint(Vb[(kk * 8 + lr) * VSTR + dt * 8 + lq]);
                uint32_t b1 = __float_as_uint(Vb[(kk * 8 + lr + 4) * VSTR + dt * 8 + lq]);
                mma_tf32(oacc[dt], pa0[kk], pa1[kk], pa2[kk], pa3[kk], b0, b1);
            }
        }
    }

    // ---- epilogue (store tf32-rounded for O-proj GEMM) ----
    float inv0 = 1.f / l0;
    float inv1 = 1.f / l1;
#pragma unroll
    for (int dt = 0; dt < 8; dt++) {
        int col = dt * 8 + 2 * lr;
        *(float2*)(O + base + (size_t)gq0 * D_MODEL + col) =
            make_float2(f2tf(oacc[dt][0] * inv0), f2tf(oacc[dt][1] * inv0));
        *(float2*)(O + base + (size_t)gq1 * D_MODEL + col) =
            make_float2(f2tf(oacc[dt][2] * inv1), f2tf(oacc[dt][3] * inv1));
    }
}

// =====================================================================
// launch
// =====================================================================
extern "C" void kernel_launch(void* const* d_in, const int* in_sizes, int n_in,
                              void* d_out, int out_size) {
    const float* x    = (const float*)d_in[0];
    const float* W_kv = (const float*)d_in[1];
    const float* W_k  = (const float*)d_in[2];
    const float* W_v  = (const float*)d_in[3];
    const float* W_q  = (const float*)d_in[4];
    const float* W_o  = (const float*)d_in[5];
    float* out = (float*)d_out;

    const int BT = in_sizes[0] / D_MODEL;   // 8192
    const int T  = T_SEQ;
    const int B  = BT / T;

    float *lat, *Kf, *Vf, *Qf, *Of, *Xr, *Wqr, *Wor;
    cudaGetSymbolAddress((void**)&lat, g_lat);
    cudaGetSymbolAddress((void**)&Kf,  g_K);
    cudaGetSymbolAddress((void**)&Vf,  g_V);
    cudaGetSymbolAddress((void**)&Qf,  g_Q);
    cudaGetSymbolAddress((void**)&Of,  g_O);
    cudaGetSymbolAddress((void**)&Xr,  g_X);
    cudaGetSymbolAddress((void**)&Wqr, g_Wq);
    cudaGetSymbolAddress((void**)&Wor, g_Wo);

    const int attn_smem = (2 * KSZ + 2 * VSZ + P_REGION) * (int)sizeof(float);
    cudaFuncSetAttribute(attn_kernel, cudaFuncAttributeMaxDynamicSharedMemorySize,
                         attn_smem);

    // 0. pre-round inputs for tf32 GEMMs
    {
        int n4 = BT * D_MODEL / 4;
        round_kernel<<<(n4 + 255) / 256, 256>>>(x, Xr, n4);
        int w4 = D_MODEL * D_MODEL / 4;
        round_kernel<<<(w4 + 255) / 256, 256>>>(W_q, Wqr, w4);
        round_kernel<<<(w4 + 255) / 256, 256>>>(W_o, Wor, w4);
    }

    // 1. lat = x @ W_kv (exact fp32)
    lat_kernel<<<BT / 32, 256>>>(x, W_kv, lat);

    // 2. K,V = lat @ W_k / W_v (exact fp32, tf32-rounded stores)
    kv_kernel<<<BT / 4, 256>>>(lat, W_k, W_v, Kf, Vf);

    // 3. Q = x @ W_q (tf32, round output for attention)
    dim3 gq(D_MODEL / 128, BT / 128);
    gemm_tf32<<<gq, 256>>>(Xr, Wqr, Qf, BT, D_MODEL, D_MODEL, 1);

    // 4. causal flash attention
    dim3 ga(T / 128, B * N_HEADS);
    attn_kernel<<<ga, 256, attn_smem>>>(Qf, Kf, Vf, Of, T);

    // 5. out = O @ W_o (tf32)
    gemm_tf32<<<gq, 256>>>(Of, Wor, out, BT, D_MODEL, D_MODEL, 0);
}

// round 5
// speedup vs baseline: 1.6685x; 1.6685x over previous
#include <cuda_runtime.h>
#include <cuda_bf16.h>
#include <cstdint>

// ---------------- problem constants ----------------
#define D_MODEL 1024
#define N_HEADS 16
#define D_HEAD  64
#define LATENT  32
#define T_SEQ   4096
#define NEG_INF (-1e9f)

// ---------------- device scratch (no allocs allowed) ----------------
#define MAX_BT 8192
__device__ float g_lat [MAX_BT * LATENT];            // tf32-rounded lat  [BT,32]
__device__ float g_latT[2 * LATENT * T_SEQ];         // lat^T per batch   [B][32][T]
__device__ float g_Qp  [MAX_BT * 512];               // Q' = x @ W_qk     [BT,512]
__device__ float g_O   [MAX_BT * 512];               // O' = attn @ lat   [BT,512]
__device__ float g_X   [MAX_BT * D_MODEL];           // tf32-rounded x
__device__ float g_Wqk [D_MODEL * 512];              // folded Q/K weights
__device__ float g_Wvo [512 * D_MODEL];              // folded V/O weights

// ---------------- helpers ----------------
__device__ __forceinline__ float f2tf(float f) {
    uint32_t u;
    asm("cvt.rna.tf32.f32 %0, %1;" : "=r"(u) : "f"(f));
    return __uint_as_float(u);
}
__device__ __forceinline__ void mma_tf32(float c[4],
                                         uint32_t a0, uint32_t a1, uint32_t a2, uint32_t a3,
                                         uint32_t b0, uint32_t b1) {
    asm volatile(
        "mma.sync.aligned.m16n8k8.row.col.f32.tf32.tf32.f32 "
        "{%0,%1,%2,%3},{%4,%5,%6,%7},{%8,%9},{%0,%1,%2,%3};"
        : "+f"(c[0]), "+f"(c[1]), "+f"(c[2]), "+f"(c[3])
        : "r"(a0), "r"(a1), "r"(a2), "r"(a3), "r"(b0), "r"(b1));
}
__device__ __forceinline__ void cp16(uint32_t s, const void* g) {
    asm volatile("cp.async.cg.shared.global [%0], [%1], 16;" :: "r"(s), "l"(g));
}
__device__ __forceinline__ void cp_commit() {
    asm volatile("cp.async.commit_group;");
}
__device__ __forceinline__ void cp_wait_all() {
    asm volatile("cp.async.wait_group 0;");
}

// =====================================================================
// Kernel 0: elementwise tf32 rounding (float4)
// =====================================================================
__global__ void round_kernel(const float* __restrict__ src,
                             float* __restrict__ dst, int n4) {
    int i = blockIdx.x * blockDim.x + threadIdx.x;
    if (i < n4) {
        float4 v = ((const float4*)src)[i];
        ((float4*)dst)[i] = make_float4(f2tf(v.x), f2tf(v.y), f2tf(v.z), f2tf(v.w));
    }
}

// =====================================================================
// Kernel 1: lat = x @ W_kv  (fp32 exact, tf32-rounded store)
// block: 32 rows x 32 cols, cp.async double-buffered k-chunks of 64.
// =====================================================================
#define LXS 68
__global__ __launch_bounds__(256)
void lat_kernel(const float* __restrict__ x,
                const float* __restrict__ Wkv,
                float* __restrict__ lat) {
    __shared__ float xs[2][32 * LXS];
    __shared__ float ws[2][64 * 32];
    const int tid = threadIdx.x;
    const int col = tid & 31;
    const int rg  = tid >> 5;          // 0..7 -> rows rg*4..rg*4+3
    const int row0 = blockIdx.x * 32;
    uint32_t xss = __cvta_generic_to_shared(xs);
    uint32_t wss = __cvta_generic_to_shared(ws);

    auto issue = [&](int c, int buf) {
#pragma unroll
        for (int i = 0; i < 2; i++) {
            int idx = tid + i * 256;          // 0..511
            int r = idx >> 4, ch = idx & 15;  // 32 rows x 16 chunks (64 floats)
            cp16(xss + (uint32_t)(buf * 32 * LXS + r * LXS + ch * 4) * 4,
                 x + (size_t)(row0 + r) * D_MODEL + c * 64 + ch * 4);
        }
#pragma unroll
        for (int i = 0; i < 2; i++) {
            int idx = tid + i * 256;
            int kr = idx >> 3, ch = idx & 7;  // 64 rows x 8 chunks (32 floats)
            cp16(wss + (uint32_t)(buf * 64 * 32 + kr * 32 + ch * 4) * 4,
                 Wkv + (size_t)(c * 64 + kr) * LATENT + ch * 4);
        }
        cp_commit();
    };

    float acc[4] = {0.f, 0.f, 0.f, 0.f};
    issue(0, 0);
    for (int c = 0; c < 16; c++) {
        cp_wait_all();
        __syncthreads();
        if (c + 1 < 16) issue(c + 1, (c + 1) & 1);
        const float* xb = xs[c & 1];
        const float* wb = ws[c & 1];
#pragma unroll 8
        for (int kk = 0; kk < 64; kk++) {
            float w = wb[kk * 32 + col];
#pragma unroll
            for (int r = 0; r < 4; r++)
                acc[r] += xb[(rg * 4 + r) * LXS + kk] * w;
        }
        __syncthreads();
    }
#pragma unroll
    for (int r = 0; r < 4; r++)
        lat[(size_t)(row0 + rg * 4 + r) * LATENT + col] = f2tf(acc[r]);
}

// =====================================================================
// Kernel 1b: latT[b][l][t] = lat[b*T+t][l]
// =====================================================================
__global__ void transpose_lat(const float* __restrict__ lat,
                              float* __restrict__ latT, int T) {
    __shared__ float ts[128 * 33];
    const int tid = threadIdx.x;
    const int bt0 = blockIdx.x * 128;
    const int b = bt0 / T;
    const int t0 = bt0 % T;
#pragma unroll
    for (int i = tid; i < 128 * 32; i += 256) {
        int t = i >> 5, l = i & 31;
        ts[t * 33 + l] = lat[(size_t)(bt0 + t) * LATENT + l];
    }
    __syncthreads();
#pragma unroll
    for (int i = tid; i < 128 * 32; i += 256) {
        int l = i >> 7, t = i & 127;
        latT[(size_t)b * LATENT * T + (size_t)l * T + t0 + t] = ts[t * 33 + l];
    }
}

// =====================================================================
// Kernel 2a: W_qk[:, h*32+l] = sum_d W_q[:, h*64+d] * W_k[l, h*64+d]
// grid (16 heads, 16 row-tiles of 64). fp32 exact, tf32-rounded store.
// smem stride 68 (multiple of 4 -> float4-aligned stores).
// =====================================================================
#define WQS 68
__global__ void wqk_kernel(const float* __restrict__ Wq,
                           const float* __restrict__ Wk,
                           float* __restrict__ Wqk) {
    __shared__ float As[64 * WQS];
    __shared__ float Bs[32 * WQS];
    const int tid = threadIdx.x;
    const int h = blockIdx.x;
    const int rt = blockIdx.y;
#pragma unroll
    for (int i = 0; i < 4; i++) {
        int idx = tid + i * 256;              // 1024 float4 for A
        int r = idx >> 4, c4 = (idx & 15) * 4;
        float4 v = *(const float4*)(Wq + (size_t)(rt * 64 + r) * D_MODEL + h * 64 + c4);
        *(float4*)(&As[r * WQS + c4]) = v;
    }
#pragma unroll
    for (int i = 0; i < 2; i++) {
        int idx = tid + i * 256;              // 512 float4 for B
        int r = idx >> 4, c4 = (idx & 15) * 4;
        float4 v = *(const float4*)(Wk + (size_t)r * D_MODEL + h * 64 + c4);
        *(float4*)(&Bs[r * WQS + c4]) = v;
    }
    __syncthreads();
    const int l = tid & 31;
    const int rg = tid >> 5;
    float acc[8] = {0,0,0,0,0,0,0,0};
#pragma unroll 8
    for (int d = 0; d < 64; d++) {
        float b = Bs[l * WQS + d];
#pragma unroll
        for (int r = 0; r < 8; r++)
            acc[r] += As[(rg * 8 + r) * WQS + d] * b;
    }
#pragma unroll
    for (int r = 0; r < 8; r++)
        Wqk[(size_t)(rt * 64 + rg * 8 + r) * 512 + h * 32 + l] = f2tf(acc[r]);
}

// =====================================================================
// Kernel 2b: W_vo[h*32+l, :] = sum_d W_v[l, h*64+d] * W_o[h*64+d, :]
// grid (16 heads, 8 col-tiles of 128). fp32 exact, tf32-rounded store.
// =====================================================================
__global__ void wvo_kernel(const float* __restrict__ Wv,
                           const float* __restrict__ Wo,
                           float* __restrict__ Wvo) {
    __shared__ float wvs[32 * WQS];
    __shared__ float wos[64 * 132];
    const int tid = threadIdx.x;
    const int h = blockIdx.x;
    const int ot = blockIdx.y;
#pragma unroll
    for (int i = 0; i < 2; i++) {
        int idx = tid + i * 256;
        int r = idx >> 4, c4 = (idx & 15) * 4;
        float4 v = *(const float4*)(Wv + (size_t)r * D_MODEL + h * 64 + c4);
        *(float4*)(&wvs[r * WQS + c4]) = v;
    }
#pragma unroll
    for (int i = 0; i < 8; i++) {
        int idx = tid + i * 256;              // 2048 float4: 64 rows x 32 f4
        int d = idx >> 5, c4 = (idx & 31) * 4;
        float4 v = *(const float4*)(Wo + (size_t)(h * 64 + d) * D_MODEL + ot * 128 + c4);
        *(float4*)(&wos[d * 132 + c4]) = v;
    }
    __syncthreads();
    const int l = tid & 31;
    const int og = tid >> 5;
    float acc[16];
#pragma unroll
    for (int j = 0; j < 16; j++) acc[j] = 0.f;
#pragma unroll 4
    for (int d = 0; d < 64; d++) {
        float wv = wvs[l * WQS + d];
#pragma unroll
        for (int j = 0; j < 16; j++)
            acc[j] += wv * wos[d * 132 + og * 16 + j];
    }
#pragma unroll
    for (int j = 0; j < 16; j++)
        Wvo[(size_t)(h * 32 + l) * D_MODEL + ot * 128 + og * 16 + j] = f2tf(acc[j]);
}

// =====================================================================
// Kernel 3/5: tf32 MMA GEMM, cp.async double-buffered (pre-rounded in).
// =====================================================================
#define GA 36
#define GB 136
#define GA_SZ (128 * GA)
#define GB_SZ (16 * GB)
__global__ __launch_bounds__(256, 2)
void gemm_tf32(const float* __restrict__ A,
               const float* __restrict__ B,
               float* __restrict__ C,
               int M, int N, int K, int round_out) {
    __shared__ float As[2 * GA_SZ];
    __shared__ float Bs[2 * GB_SZ];
    const int tid = threadIdx.x;
    const int lane = tid & 31;
    const int wid = tid >> 5;
    const int bm = blockIdx.y * 128;
    const int bn = blockIdx.x * 128;
    const int wm = (wid >> 2) * 64;
    const int wn = (wid & 3) * 32;
    const int lq = lane >> 2;
    const int lr = lane & 3;
    uint32_t asb = __cvta_generic_to_shared(As);
    uint32_t bsb = __cvta_generic_to_shared(Bs);

    float acc[4][4][4];
#pragma unroll
    for (int mt = 0; mt < 4; mt++)
#pragma unroll
        for (int nt = 0; nt < 4; nt++)
#pragma unroll
            for (int j = 0; j < 4; j++) acc[mt][nt][j] = 0.f;

    auto issue_stage = [&](int k0, int buf) {
#pragma unroll
        for (int i = 0; i < 2; i++) {
            int idx = tid + i * 256;
            int row = idx >> 2, ch = idx & 3;
            cp16(asb + (uint32_t)(buf * GA_SZ + row * GA + ch * 4) * 4,
                 A + (size_t)(bm + row) * K + k0 + ch * 4);
        }
#pragma unroll
        for (int i = 0; i < 2; i++) {
            int idx = tid + i * 256;
            int row = idx >> 5, ch = idx & 31;
            cp16(bsb + (uint32_t)(buf * GB_SZ + row * GB + ch * 4) * 4,
                 B + (size_t)(k0 + row) * N + bn + ch * 4);
        }
        cp_commit();
    };

    issue_stage(0, 0);
    const int niter = K / 16;
    for (int it = 0; it < niter; it++) {
        cp_wait_all();
        __syncthreads();
        if (it + 1 < niter) issue_stage((it + 1) * 16, (it + 1) & 1);
        const float* Ab = As + (it & 1) * GA_SZ;
        const float* Bb = Bs + (it & 1) * GB_SZ;
#pragma unroll
        for (int kk = 0; kk < 16; kk += 8) {
            uint32_t a[4][4];
#pragma unroll
            for (int mt = 0; mt < 4; mt++) {
                int r = wm + mt * 16 + lq;
                a[mt][0] = __float_as_uint(Ab[r * GA + kk + lr]);
                a[mt][1] = __float_as_uint(Ab[(r + 8) * GA + kk + lr]);
                a[mt][2] = __float_as_uint(Ab[r * GA + kk + lr + 4]);
                a[mt][3] = __float_as_uint(Ab[(r + 8) * GA + kk + lr + 4]);
            }
#pragma unroll
            for (int nt = 0; nt < 4; nt++) {
                uint32_t b0 = __float_as_uint(Bb[(kk + lr) * GB + wn + nt * 8 + lq]);
                uint32_t b1 = __float_as_uint(Bb[(kk + lr + 4) * GB + wn + nt * 8 + lq]);
#pragma unroll
                for (int mt = 0; mt < 4; mt++)
                    mma_tf32(acc[mt][nt], a[mt][0], a[mt][1], a[mt][2], a[mt][3], b0, b1);
            }
        }
        __syncthreads();
    }

#pragma unroll
    for (int mt = 0; mt < 4; mt++) {
        int r0 = bm + wm + mt * 16 + lq;
#pragma unroll
        for (int nt = 0; nt < 4; nt++) {
            int col = bn + wn + nt * 8 + 2 * lr;
            float v0 = acc[mt][nt][0], v1 = acc[mt][nt][1];
            float v2 = acc[mt][nt][2], v3 = acc[mt][nt][3];
            if (round_out) { v0 = f2tf(v0); v1 = f2tf(v1); v2 = f2tf(v2); v3 = f2tf(v3); }
            *(float2*)(C + (size_t)r0 * N + col)       = make_float2(v0, v1);
            *(float2*)(C + (size_t)(r0 + 8) * N + col) = make_float2(v2, v3);
        }
    }
}

// =====================================================================
// Kernel 4: latent-space causal flash attention, tf32 MMA.
// S = Q'(128x32) @ lat^T, O' = P(128x64) @ lat(64x32).
// 256 thr / 8 warps; q-tile 128; k-tile 64; shared lat tile both MMAs.
// =====================================================================
#define LS_STR 36
#define LT_STR 68
#define LS_SZ (64 * LS_STR)
#define LT_SZ (32 * LT_STR)
#define PGRP 132
#define PWARP (8 * PGRP)
#define QS_STR 36
#define P_REGION (8 * PWARP)
__global__ __launch_bounds__(256, 2)
void attn_kernel(const float* __restrict__ Qp,
                 const float* __restrict__ lat,
                 const float* __restrict__ latT,
                 float* __restrict__ O,
                 int T) {
    extern __shared__ float sm[];
    float* Ls = sm;                          // [2][64][LS_STR]  lat[key][l]
    float* Lt = Ls + 2 * LS_SZ;              // [2][32][LT_STR]  lat^T[l][key]
    float* Ps = Lt + 2 * LT_SZ;              // P / Q' staging

    const int qt  = (gridDim.x - 1) - blockIdx.x;
    const int bh  = blockIdx.y;
    const int b   = bh >> 4;
    const int h   = bh & 15;
    const int tid = threadIdx.x;
    const int wid = tid >> 5;
    const int lane = tid & 31;
    const int lq = lane >> 2;
    const int lr = lane & 3;
    const float scale = 0.125f;

    const float* latg  = lat + (size_t)b * T * LATENT;
    const float* latTg = latT + (size_t)b * LATENT * T;
    uint32_t lss = __cvta_generic_to_shared(Ls);
    uint32_t lts = __cvta_generic_to_shared(Lt);

    auto issue_tile = [&](int kt, int buf) {
#pragma unroll
        for (int i = 0; i < 2; i++) {
            int c = tid + i * 256;             // 512: 64 rows x 8 chunks
            int row = c >> 3, ch = c & 7;
            cp16(lss + (uint32_t)(buf * LS_SZ + row * LS_STR + ch * 4) * 4,
                 latg + (size_t)(kt * 64 + row) * LATENT + ch * 4);
        }
#pragma unroll
        for (int i = 0; i < 2; i++) {
            int c = tid + i * 256;             // 512: 32 rows x 16 chunks
            int row = c >> 4, ch = c & 15;
            cp16(lts + (uint32_t)(buf * LT_SZ + row * LT_STR + ch * 4) * 4,
                 latTg + (size_t)row * T + kt * 64 + ch * 4);
        }
        cp_commit();
    };

    issue_tile(0, 0);

    // ---- Q' tile [128 x 32] -> stage -> register fragments ----
    const size_t qbase = (size_t)(b * T + qt * 128) * 512 + h * LATENT;
#pragma unroll
    for (int i = tid; i < 128 * 8; i += 256) {
        int q = i >> 3, c4 = (i & 7) * 4;
        float4 v = *(const float4*)(Qp + qbase + (size_t)q * 512 + c4);
        *(float4*)(&Ps[q * QS_STR + c4]) = v;
    }
    __syncthreads();
    uint32_t qa0[4], qa1[4], qa2[4], qa3[4];
    {
        int r0 = wid * 16 + lq;
#pragma unroll
        for (int kk = 0; kk < 4; kk++) {
            qa0[kk] = __float_as_uint(Ps[r0 * QS_STR + kk * 8 + lr]);
            qa1[kk] = __float_as_uint(Ps[(r0 + 8) * QS_STR + kk * 8 + lr]);
            qa2[kk] = __float_as_uint(Ps[r0 * QS_STR + kk * 8 + lr + 4]);
            qa3[kk] = __float_as_uint(Ps[(r0 + 8) * QS_STR + kk * 8 + lr + 4]);
        }
    }
    __syncthreads();

    float oacc[4][4];
#pragma unroll
    for (int dt = 0; dt < 4; dt++)
#pragma unroll
        for (int j = 0; j < 4; j++) oacc[dt][j] = 0.f;
    float m0 = -1e30f, m1 = -1e30f, l0 = 0.f, l1 = 0.f;

    const int gq0 = qt * 128 + wid * 16 + lq;
    const int gq1 = gq0 + 8;
    const int kt_max = 2 * qt + 1;

    for (int kt = 0; kt <= kt_max; kt++) {
        cp_wait_all();
        __syncthreads();
        if (kt < kt_max) issue_tile(kt + 1, (kt + 1) & 1);

        const float* Lsb = Ls + (kt & 1) * LS_SZ;
        const float* Ltb = Lt + (kt & 1) * LT_SZ;

        // ---- S = Q' lat^T : warp 16 x 64, k-dim 32 ----
        float sacc[8][4];
#pragma unroll
        for (int n = 0; n < 8; n++)
#pragma unroll
            for (int j = 0; j < 4; j++) sacc[n][j] = 0.f;
#pragma unroll
        for (int kk = 0; kk < 4; kk++) {
#pragma unroll
            for (int n = 0; n < 8; n++) {
                uint32_t b0 = __float_as_uint(Lsb[(n * 8 + lq) * LS_STR + kk * 8 + lr]);
                uint32_t b1 = __float_as_uint(Lsb[(n * 8 + lq) * LS_STR + kk * 8 + lr + 4]);
                mma_tf32(sacc[n], qa0[kk], qa1[kk], qa2[kk], qa3[kk], b0, b1);
            }
        }

        // ---- scale + causal mask ----
        const bool needmask = (kt >= 2 * qt);
#pragma unroll
        for (int n = 0; n < 8; n++) {
#pragma unroll
            for (int j = 0; j < 4; j++) {
                float v = sacc[n][j] * scale;
                if (needmask) {
                    int gk = kt * 64 + n * 8 + 2 * lr + (j & 1);
                    int gq = (j < 2) ? gq0 : gq1;
                    if (gk > gq) v += NEG_INF;
                }
                sacc[n][j] = v;
            }
        }

        // ---- online softmax ----
        float mx0 = -1e30f, mx1 = -1e30f;
#pragma unroll
        for (int n = 0; n < 8; n++) {
            mx0 = fmaxf(mx0, fmaxf(sacc[n][0], sacc[n][1]));
            mx1 = fmaxf(mx1, fmaxf(sacc[n][2], sacc[n][3]));
        }
        mx0 = fmaxf(mx0, __shfl_xor_sync(0xffffffffu, mx0, 1));
        mx0 = fmaxf(mx0, __shfl_xor_sync(0xffffffffu, mx0, 2));
        mx1 = fmaxf(mx1, __shfl_xor_sync(0xffffffffu, mx1, 1));
        mx1 = fmaxf(mx1, __shfl_xor_sync(0xffffffffu, mx1, 2));
        float mn0 = fmaxf(m0, mx0);
        float mn1 = fmaxf(m1, mx1);
        float c0 = __expf(m0 - mn0);
        float c1 = __expf(m1 - mn1);
        float s0 = 0.f, s1 = 0.f;
#pragma unroll
        for (int n = 0; n < 8; n++) {
            sacc[n][0] = __expf(sacc[n][0] - mn0);
            sacc[n][1] = __expf(sacc[n][1] - mn0);
            sacc[n][2] = __expf(sacc[n][2] - mn1);
            sacc[n][3] = __expf(sacc[n][3] - mn1);
            s0 += sacc[n][0] + sacc[n][1];
            s1 += sacc[n][2] + sacc[n][3];
        }
        s0 += __shfl_xor_sync(0xffffffffu, s0, 1);
        s0 += __shfl_xor_sync(0xffffffffu, s0, 2);
        s1 += __shfl_xor_sync(0xffffffffu, s1, 1);
        s1 += __shfl_xor_sync(0xffffffffu, s1, 2);
        l0 = l0 * c0 + s0;
        l1 = l1 * c1 + s1;
        m0 = mn0; m1 = mn1;
#pragma unroll
        for (int dt = 0; dt < 4; dt++) {
            oacc[dt][0] *= c0; oacc[dt][1] *= c0;
            oacc[dt][2] *= c1; oacc[dt][3] *= c1;
        }

        // ---- P -> fragment-major smem (tf32) ----
        {
            float* Pw = Ps + wid * PWARP;
#pragma unroll
            for (int n = 0; n < 8; n++) {
#pragma unroll
                for (int j = 0; j < 4; j++) {
                    int cfull = 2 * lr + (j & 1);
                    int hc = cfull >> 2, lra = cfull & 3;
                    int hr = j >> 1;
                    int grp = (hr * 2 + hc) * 2 + (n >> 2);
                    Pw[grp * PGRP + (lq * 4 + lra) * 4 + (n & 3)] = f2tf(sacc[n][j]);
                }
            }
        }
        __syncwarp();

        // ---- P fragments (vectorized) ----
        uint32_t pa0[8], pa1[8], pa2[8], pa3[8];
        {
            const float* Pw = Ps + wid * PWARP;
#pragma unroll
            for (int q = 0; q < 2; q++) {
                float4 v00 = *(const float4*)(&Pw[((0 * 2 + 0) * 2 + q) * PGRP + lane * 4]);
                float4 v10 = *(const float4*)(&Pw[((1 * 2 + 0) * 2 + q) * PGRP + lane * 4]);
                float4 v01 = *(const float4*)(&Pw[((0 * 2 + 1) * 2 + q) * PGRP + lane * 4]);
                float4 v11 = *(const float4*)(&Pw[((1 * 2 + 1) * 2 + q) * PGRP + lane * 4]);
                pa0[q*4+0]=__float_as_uint(v00.x); pa0[q*4+1]=__float_as_uint(v00.y);
                pa0[q*4+2]=__float_as_uint(v00.z); pa0[q*4+3]=__float_as_uint(v00.w);
                pa1[q*4+0]=__float_as_uint(v10.x); pa1[q*4+1]=__float_as_uint(v10.y);
                pa1[q*4+2]=__float_as_uint(v10.z); pa1[q*4+3]=__float_as_uint(v10.w);
                pa2[q*4+0]=__float_as_uint(v01.x); pa2[q*4+1]=__float_as_uint(v01.y);
                pa2[q*4+2]=__float_as_uint(v01.z); pa2[q*4+3]=__float_as_uint(v01.w);
                pa3[q*4+0]=__float_as_uint(v11.x); pa3[q*4+1]=__float_as_uint(v11.y);
                pa3[q*4+2]=__float_as_uint(v11.z); pa3[q*4+3]=__float_as_uint(v11.w);
            }
        }

        // ---- O' += P lat : warp 16 x 32, k-dim 64 ----
#pragma unroll
        for (int dt = 0; dt < 4; dt++) {
#pragma unroll
            for (int kk = 0; kk < 8; kk++) {
                uint32_t b0 = __float_as_uint(Ltb[(dt * 8 + lq) * LT_STR + kk * 8 + lr]);
                uint32_t b1 = __float_as_uint(Ltb[(dt * 8 + lq) * LT_STR + kk * 8 + lr + 4]);
                mma_tf32(oacc[dt], pa0[kk], pa1[kk], pa2[kk], pa3[kk], b0, b1);
            }
        }
    }

    // ---- epilogue: O' [128 x 32] tf32-rounded ----
    float inv0 = 1.f / l0;
    float inv1 = 1.f / l1;
    const size_t obase = (size_t)(b * T) * 512 + h * LATENT;
#pragma unroll
    for (int dt = 0; dt < 4; dt++) {
        int col = dt * 8 + 2 * lr;
        *(float2*)(O + obase + (size_t)gq0 * 512 + col) =
            make_float2(f2tf(oacc[dt][0] * inv0), f2tf(oacc[dt][1] * inv0));
        *(float2*)(O + obase + (size_t)gq1 * 512 + col) =
            make_float2(f2tf(oacc[dt][2] * inv1), f2tf(oacc[dt][3] * inv1));
    }
}

// =====================================================================
// launch
// =====================================================================
extern "C" void kernel_launch(void* const* d_in, const int* in_sizes, int n_in,
                              void* d_out, int out_size) {
    const float* x    = (const float*)d_in[0];
    const float* W_kv = (const float*)d_in[1];
    const float* W_k  = (const float*)d_in[2];
    const float* W_v  = (const float*)d_in[3];
    const float* W_q  = (const float*)d_in[4];
    const float* W_o  = (const float*)d_in[5];
    float* out = (float*)d_out;

    const int BT = in_sizes[0] / D_MODEL;   // 8192
    const int T  = T_SEQ;
    const int B  = BT / T;

    float *lat, *latT, *Qf, *Of, *Xr, *Wqk, *Wvo;
    cudaGetSymbolAddress((void**)&lat,  g_lat);
    cudaGetSymbolAddress((void**)&latT, g_latT);
    cudaGetSymbolAddress((void**)&Qf,   g_Qp);
    cudaGetSymbolAddress((void**)&Of,   g_O);
    cudaGetSymbolAddress((void**)&Xr,   g_X);
    cudaGetSymbolAddress((void**)&Wqk,  g_Wqk);
    cudaGetSymbolAddress((void**)&Wvo,  g_Wvo);

    const int attn_smem = (2 * LS_SZ + 2 * LT_SZ + P_REGION) * (int)sizeof(float);
    cudaFuncSetAttribute(attn_kernel, cudaFuncAttributeMaxDynamicSharedMemorySize,
                         attn_smem);

    // 0. pre-round x for the Q' GEMM
    {
        int n4 = BT * D_MODEL / 4;
        round_kernel<<<(n4 + 255) / 256, 256>>>(x, Xr, n4);
    }

    // 1. lat = x @ W_kv (exact fp32, tf32-rounded store) + transpose
    lat_kernel<<<BT / 32, 256>>>(x, W_kv, lat);
    transpose_lat<<<BT / 128, 256>>>(lat, latT, T);

    // 2. folded weights
    wqk_kernel<<<dim3(N_HEADS, 16), 256>>>(W_q, W_k, Wqk);
    wvo_kernel<<<dim3(N_HEADS, 8), 256>>>(W_v, W_o, Wvo);

    // 3. Q' = x @ W_qk  [8192x1024x512]
    gemm_tf32<<<dim3(512 / 128, BT / 128), 256>>>(Xr, Wqk, Qf, BT, 512, D_MODEL, 1);

    // 4. latent-space causal flash attention
    dim3 ga(T / 128, B * N_HEADS);
    attn_kernel<<<ga, 256, attn_smem>>>(Qf, lat, latT, Of, T);

    // 5. out = O' @ W_vo  [8192x512x1024]
    gemm_tf32<<<dim3(D_MODEL / 128, BT / 128), 256>>>(Of, Wvo, out, BT, D_MODEL, 512, 0);
}

// round 6
// speedup vs baseline: 1.7770x; 1.0650x over previous
#include <cuda_runtime.h>
#include <cuda_bf16.h>
#include <cstdint>

// ---------------- problem constants ----------------
#define D_MODEL 1024
#define N_HEADS 16
#define D_HEAD  64
#define LATENT  32
#define T_SEQ   4096
#define NEG_INF (-1e9f)

// ---------------- device scratch (no allocs allowed) ----------------
#define MAX_BT 8192
__device__ float g_lat [MAX_BT * LATENT];            // tf32-rounded lat  [BT,32]
__device__ float g_latT[2 * LATENT * T_SEQ];         // lat^T per batch   [B][32][T]
__device__ float g_Qp  [MAX_BT * 512];               // Q' = x @ W_qk     [BT,512]
__device__ float g_O   [MAX_BT * 512];               // O' = attn @ lat   [BT,512]
__device__ float g_X   [MAX_BT * D_MODEL];           // tf32-rounded x
__device__ float g_Wqk [D_MODEL * 512];              // folded Q/K weights
__device__ float g_Wvo [512 * D_MODEL];              // folded V/O weights

// ---------------- helpers ----------------
__device__ __forceinline__ float f2tf(float f) {
    uint32_t u;
    asm("cvt.rna.tf32.f32 %0, %1;" : "=r"(u) : "f"(f));
    return __uint_as_float(u);
}
__device__ __forceinline__ float fexp2(float x) {
    float r;
    asm("ex2.approx.f32 %0, %1;" : "=f"(r) : "f"(x));
    return r;
}
__device__ __forceinline__ void mma_tf32(float c[4],
                                         uint32_t a0, uint32_t a1, uint32_t a2, uint32_t a3,
                                         uint32_t b0, uint32_t b1) {
    asm volatile(
        "mma.sync.aligned.m16n8k8.row.col.f32.tf32.tf32.f32 "
        "{%0,%1,%2,%3},{%4,%5,%6,%7},{%8,%9},{%0,%1,%2,%3};"
        : "+f"(c[0]), "+f"(c[1]), "+f"(c[2]), "+f"(c[3])
        : "r"(a0), "r"(a1), "r"(a2), "r"(a3), "r"(b0), "r"(b1));
}
__device__ __forceinline__ void cp16(uint32_t s, const void* g) {
    asm volatile("cp.async.cg.shared.global [%0], [%1], 16;" :: "r"(s), "l"(g));
}
__device__ __forceinline__ void cp_commit() {
    asm volatile("cp.async.commit_group;");
}

// =====================================================================
// Kernel 0: elementwise tf32 rounding (float4)
// =====================================================================
__global__ void round_kernel(const float* __restrict__ src,
                             float* __restrict__ dst, int n4) {
    int i = blockIdx.x * blockDim.x + threadIdx.x;
    if (i < n4) {
        float4 v = ((const float4*)src)[i];
        ((float4*)dst)[i] = make_float4(f2tf(v.x), f2tf(v.y), f2tf(v.z), f2tf(v.w));
    }
}

// =====================================================================
// Kernel 1: lat = x @ W_kv  (fp32 exact, tf32-rounded store)
// + fused transpose write of latT. Block: 32 bt rows.
// =====================================================================
#define LXS 68
__global__ __launch_bounds__(256)
void lat_kernel(const float* __restrict__ x,
                const float* __restrict__ Wkv,
                float* __restrict__ lat,
                float* __restrict__ latT,
                int T) {
    __shared__ float xs[2][32 * LXS];
    __shared__ float ws[2][64 * 32];
    const int tid = threadIdx.x;
    const int col = tid & 31;
    const int rg  = tid >> 5;          // 0..7 -> rows rg*4..rg*4+3
    const int row0 = blockIdx.x * 32;
    uint32_t xss = __cvta_generic_to_shared(xs);
    uint32_t wss = __cvta_generic_to_shared(ws);

    auto issue = [&](int c, int buf) {
#pragma unroll
        for (int i = 0; i < 2; i++) {
            int idx = tid + i * 256;
            int r = idx >> 4, ch = idx & 15;
            cp16(xss + (uint32_t)(buf * 32 * LXS + r * LXS + ch * 4) * 4,
                 x + (size_t)(row0 + r) * D_MODEL + c * 64 + ch * 4);
        }
#pragma unroll
        for (int i = 0; i < 2; i++) {
            int idx = tid + i * 256;
            int kr = idx >> 3, ch = idx & 7;
            cp16(wss + (uint32_t)(buf * 64 * 32 + kr * 32 + ch * 4) * 4,
                 Wkv + (size_t)(c * 64 + kr) * LATENT + ch * 4);
        }
        cp_commit();
    };

    float acc[4] = {0.f, 0.f, 0.f, 0.f};
    issue(0, 0);
    for (int c = 0; c < 16; c++) {
        asm volatile("cp.async.wait_group 0;");
        __syncthreads();
        if (c + 1 < 16) issue(c + 1, (c + 1) & 1);
        const float* xb = xs[c & 1];
        const float* wb = ws[c & 1];
#pragma unroll 8
        for (int kk = 0; kk < 64; kk++) {
            float w = wb[kk * 32 + col];
#pragma unroll
            for (int r = 0; r < 4; r++)
                acc[r] += xb[(rg * 4 + r) * LXS + kk] * w;
        }
        __syncthreads();
    }

    // stage rounded results, then write lat + latT coalesced
    float* stg = (float*)ws;          // 32 x 36 floats
    __syncthreads();
#pragma unroll
    for (int r = 0; r < 4; r++)
        stg[(rg * 4 + r) * 36 + col] = f2tf(acc[r]);
    __syncthreads();
    {
        int r = tid >> 3, l4 = (tid & 7) * 4;
        float4 v = *(const float4*)(&stg[r * 36 + l4]);
        *(float4*)(lat + (size_t)(row0 + r) * LATENT + l4) = v;
    }
    {
        int l = tid >> 3, t4 = (tid & 7) * 4;
        int b = row0 / T, t0 = row0 % T;
        float4 v = make_float4(stg[(t4 + 0) * 36 + l], stg[(t4 + 1) * 36 + l],
                               stg[(t4 + 2) * 36 + l], stg[(t4 + 3) * 36 + l]);
        *(float4*)(latT + (size_t)b * LATENT * T + (size_t)l * T + t0 + t4) = v;
    }
}

// =====================================================================
// Kernel 2a: W_qk[:, h*32+l] = sum_d W_q[:, h*64+d] * W_k[l, h*64+d]
// =====================================================================
#define WQS 68
__global__ void wqk_kernel(const float* __restrict__ Wq,
                           const float* __restrict__ Wk,
                           float* __restrict__ Wqk) {
    __shared__ float As[64 * WQS];
    __shared__ float Bs[32 * WQS];
    const int tid = threadIdx.x;
    const int h = blockIdx.x;
    const int rt = blockIdx.y;
#pragma unroll
    for (int i = 0; i < 4; i++) {
        int idx = tid + i * 256;
        int r = idx >> 4, c4 = (idx & 15) * 4;
        float4 v = *(const float4*)(Wq + (size_t)(rt * 64 + r) * D_MODEL + h * 64 + c4);
        *(float4*)(&As[r * WQS + c4]) = v;
    }
#pragma unroll
    for (int i = 0; i < 2; i++) {
        int idx = tid + i * 256;
        int r = idx >> 4, c4 = (idx & 15) * 4;
        float4 v = *(const float4*)(Wk + (size_t)r * D_MODEL + h * 64 + c4);
        *(float4*)(&Bs[r * WQS + c4]) = v;
    }
    __syncthreads();
    const int l = tid & 31;
    const int rg = tid >> 5;
    float acc[8] = {0,0,0,0,0,0,0,0};
#pragma unroll 8
    for (int d = 0; d < 64; d++) {
        float b = Bs[l * WQS + d];
#pragma unroll
        for (int r = 0; r < 8; r++)
            acc[r] += As[(rg * 8 + r) * WQS + d] * b;
    }
#pragma unroll
    for (int r = 0; r < 8; r++)
        Wqk[(size_t)(rt * 64 + rg * 8 + r) * 512 + h * 32 + l] = f2tf(acc[r]);
}

// =====================================================================
// Kernel 2b: W_vo[h*32+l, :] = sum_d W_v[l, h*64+d] * W_o[h*64+d, :]
// =====================================================================
__global__ void wvo_kernel(const float* __restrict__ Wv,
                           const float* __restrict__ Wo,
                           float* __restrict__ Wvo) {
    __shared__ float wvs[32 * WQS];
    __shared__ float wos[64 * 132];
    const int tid = threadIdx.x;
    const int h = blockIdx.x;
    const int ot = blockIdx.y;
#pragma unroll
    for (int i = 0; i < 2; i++) {
        int idx = tid + i * 256;
        int r = idx >> 4, c4 = (idx & 15) * 4;
        float4 v = *(const float4*)(Wv + (size_t)r * D_MODEL + h * 64 + c4);
        *(float4*)(&wvs[r * WQS + c4]) = v;
    }
#pragma unroll
    for (int i = 0; i < 8; i++) {
        int idx = tid + i * 256;
        int d = idx >> 5, c4 = (idx & 31) * 4;
        float4 v = *(const float4*)(Wo + (size_t)(h * 64 + d) * D_MODEL + ot * 128 + c4);
        *(float4*)(&wos[d * 132 + c4]) = v;
    }
    __syncthreads();
    const int l = tid & 31;
    const int og = tid >> 5;
    float acc[16];
#pragma unroll
    for (int j = 0; j < 16; j++) acc[j] = 0.f;
#pragma unroll 4
    for (int d = 0; d < 64; d++) {
        float wv = wvs[l * WQS + d];
#pragma unroll
        for (int j = 0; j < 16; j++)
            acc[j] += wv * wos[d * 132 + og * 16 + j];
    }
#pragma unroll
    for (int j = 0; j < 16; j++)
        Wvo[(size_t)(h * 32 + l) * D_MODEL + ot * 128 + og * 16 + j] = f2tf(acc[j]);
}

// =====================================================================
// Kernel 3/5: tf32 MMA GEMM, 3-stage cp.async pipeline (dynamic smem).
// =====================================================================
#define GA 36
#define GB 136
#define GA_SZ (128 * GA)
#define GB_SZ (16 * GB)
#define GSTG (GA_SZ + GB_SZ)
__global__ __launch_bounds__(256, 2)
void gemm_tf32(const float* __restrict__ A,
               const float* __restrict__ B,
               float* __restrict__ C,
               int M, int N, int K, int round_out) {
    extern __shared__ float gsm[];
    const int tid = threadIdx.x;
    const int lane = tid & 31;
    const int wid = tid >> 5;
    const int bm = blockIdx.y * 128;
    const int bn = blockIdx.x * 128;
    const int wm = (wid >> 2) * 64;
    const int wn = (wid & 3) * 32;
    const int lq = lane >> 2;
    const int lr = lane & 3;
    uint32_t smb = __cvta_generic_to_shared(gsm);

    float acc[4][4][4];
#pragma unroll
    for (int mt = 0; mt < 4; mt++)
#pragma unroll
        for (int nt = 0; nt < 4; nt++)
#pragma unroll
            for (int j = 0; j < 4; j++) acc[mt][nt][j] = 0.f;

    auto issue_stage = [&](int k0, int buf) {
        uint32_t base = smb + (uint32_t)(buf * GSTG) * 4;
#pragma unroll
        for (int i = 0; i < 2; i++) {
            int idx = tid + i * 256;
            int row = idx >> 2, ch = idx & 3;
            cp16(base + (uint32_t)(row * GA + ch * 4) * 4,
                 A + (size_t)(bm + row) * K + k0 + ch * 4);
        }
#pragma unroll
        for (int i = 0; i < 2; i++) {
            int idx = tid + i * 256;
            int row = idx >> 5, ch = idx & 31;
            cp16(base + (uint32_t)(GA_SZ + row * GB + ch * 4) * 4,
                 B + (size_t)(k0 + row) * N + bn + ch * 4);
        }
        cp_commit();
    };

    const int niter = K / 16;
    issue_stage(0, 0);
    if (niter > 1) issue_stage(16, 1);

    for (int it = 0; it < niter; it++) {
        if (it + 1 < niter) asm volatile("cp.async.wait_group 1;");
        else                asm volatile("cp.async.wait_group 0;");
        __syncthreads();
        if (it + 2 < niter) issue_stage((it + 2) * 16, (it + 2) % 3);

        const float* Ab = gsm + (it % 3) * GSTG;
        const float* Bb = Ab + GA_SZ;
#pragma unroll
        for (int kk = 0; kk < 16; kk += 8) {
            uint32_t a[4][4];
#pragma unroll
            for (int mt = 0; mt < 4; mt++) {
                int r = wm + mt * 16 + lq;
                a[mt][0] = __float_as_uint(Ab[r * GA + kk + lr]);
                a[mt][1] = __float_as_uint(Ab[(r + 8) * GA + kk + lr]);
                a[mt][2] = __float_as_uint(Ab[r * GA + kk + lr + 4]);
                a[mt][3] = __float_as_uint(Ab[(r + 8) * GA + kk + lr + 4]);
            }
#pragma unroll
            for (int nt = 0; nt < 4; nt++) {
                uint32_t b0 = __float_as_uint(Bb[(kk + lr) * GB + wn + nt * 8 + lq]);
                uint32_t b1 = __float_as_uint(Bb[(kk + lr + 4) * GB + wn + nt * 8 + lq]);
#pragma unroll
                for (int mt = 0; mt < 4; mt++)
                    mma_tf32(acc[mt][nt], a[mt][0], a[mt][1], a[mt][2], a[mt][3], b0, b1);
            }
        }
        __syncthreads();
    }

#pragma unroll
    for (int mt = 0; mt < 4; mt++) {
        int r0 = bm + wm + mt * 16 + lq;
#pragma unroll
        for (int nt = 0; nt < 4; nt++) {
            int col = bn + wn + nt * 8 + 2 * lr;
            float v0 = acc[mt][nt][0], v1 = acc[mt][nt][1];
            float v2 = acc[mt][nt][2], v3 = acc[mt][nt][3];
            if (round_out) { v0 = f2tf(v0); v1 = f2tf(v1); v2 = f2tf(v2); v3 = f2tf(v3); }
            *(float2*)(C + (size_t)r0 * N + col)       = make_float2(v0, v1);
            *(float2*)(C + (size_t)(r0 + 8) * N + col) = make_float2(v2, v3);
        }
    }
}

// =====================================================================
// Kernel 4: latent-space causal flash attention, tf32 MMA.
// Base-2 softmax; row sums via ones-MMA; P stored raw fp32 (HW trunc).
// =====================================================================
#define LS_STR 36
#define LT_STR 68
#define LS_SZ (64 * LS_STR)
#define LT_SZ (32 * LT_STR)
#define PGRP 132
#define PWARP (8 * PGRP)
#define QS_STR 36
#define P_REGION (8 * PWARP)
__global__ __launch_bounds__(256, 2)
void attn_kernel(const float* __restrict__ Qp,
                 const float* __restrict__ lat,
                 const float* __restrict__ latT,
                 float* __restrict__ O,
                 int T) {
    extern __shared__ float sm[];
    float* Ls = sm;                          // [2][64][LS_STR]  lat[key][l]
    float* Lt = Ls + 2 * LS_SZ;              // [2][32][LT_STR]  lat^T[l][key]
    float* Ps = Lt + 2 * LT_SZ;              // P / Q' staging

    const int qt  = (gridDim.x - 1) - blockIdx.x;
    const int bh  = blockIdx.y;
    const int b   = bh >> 4;
    const int h   = bh & 15;
    const int tid = threadIdx.x;
    const int wid = tid >> 5;
    const int lane = tid & 31;
    const int lq = lane >> 2;
    const int lr = lane & 3;
    const float scale2 = 0.125f * 1.4426950408889634f;   // 1/sqrt(64) * log2(e)
    const uint32_t ONE = 0x3f800000u;

    const float* latg  = lat + (size_t)b * T * LATENT;
    const float* latTg = latT + (size_t)b * LATENT * T;
    uint32_t lss = __cvta_generic_to_shared(Ls);
    uint32_t lts = __cvta_generic_to_shared(Lt);

    auto issue_tile = [&](int kt, int buf) {
#pragma unroll
        for (int i = 0; i < 2; i++) {
            int c = tid + i * 256;
            int row = c >> 3, ch = c & 7;
            cp16(lss + (uint32_t)(buf * LS_SZ + row * LS_STR + ch * 4) * 4,
                 latg + (size_t)(kt * 64 + row) * LATENT + ch * 4);
        }
#pragma unroll
        for (int i = 0; i < 2; i++) {
            int c = tid + i * 256;
            int row = c >> 4, ch = c & 15;
            cp16(lts + (uint32_t)(buf * LT_SZ + row * LT_STR + ch * 4) * 4,
                 latTg + (size_t)row * T + kt * 64 + ch * 4);
        }
        cp_commit();
    };

    issue_tile(0, 0);

    // ---- Q' tile [128 x 32] -> stage -> register fragments ----
    const size_t qbase = (size_t)(b * T + qt * 128) * 512 + h * LATENT;
#pragma unroll
    for (int i = tid; i < 128 * 8; i += 256) {
        int q = i >> 3, c4 = (i & 7) * 4;
        float4 v = *(const float4*)(Qp + qbase + (size_t)q * 512 + c4);
        *(float4*)(&Ps[q * QS_STR + c4]) = v;
    }
    __syncthreads();
    uint32_t qa0[4], qa1[4], qa2[4], qa3[4];
    {
        int r0 = wid * 16 + lq;
#pragma unroll
        for (int kk = 0; kk < 4; kk++) {
            qa0[kk] = __float_as_uint(Ps[r0 * QS_STR + kk * 8 + lr]);
            qa1[kk] = __float_as_uint(Ps[(r0 + 8) * QS_STR + kk * 8 + lr]);
            qa2[kk] = __float_as_uint(Ps[r0 * QS_STR + kk * 8 + lr + 4]);
            qa3[kk] = __float_as_uint(Ps[(r0 + 8) * QS_STR + kk * 8 + lr + 4]);
        }
    }
    __syncthreads();

    float oacc[4][4];
#pragma unroll
    for (int dt = 0; dt < 4; dt++)
#pragma unroll
        for (int j = 0; j < 4; j++) oacc[dt][j] = 0.f;
    float m0 = -1e30f, m1 = -1e30f, l0 = 0.f, l1 = 0.f;

    const int gq0 = qt * 128 + wid * 16 + lq;
    const int gq1 = gq0 + 8;
    const int kt_max = 2 * qt + 1;

    for (int kt = 0; kt <= kt_max; kt++) {
        asm volatile("cp.async.wait_group 0;");
        __syncthreads();
        if (kt < kt_max) issue_tile(kt + 1, (kt + 1) & 1);

        const float* Lsb = Ls + (kt & 1) * LS_SZ;
        const float* Ltb = Lt + (kt & 1) * LT_SZ;

        // ---- S = Q' lat^T : warp 16 x 64, k-dim 32 ----
        float sacc[8][4];
#pragma unroll
        for (int n = 0; n < 8; n++)
#pragma unroll
            for (int j = 0; j < 4; j++) sacc[n][j] = 0.f;
#pragma unroll
        for (int kk = 0; kk < 4; kk++) {
#pragma unroll
            for (int n = 0; n < 8; n++) {
                uint32_t b0 = __float_as_uint(Lsb[(n * 8 + lq) * LS_STR + kk * 8 + lr]);
                uint32_t b1 = __float_as_uint(Lsb[(n * 8 + lq) * LS_STR + kk * 8 + lr + 4]);
                mma_tf32(sacc[n], qa0[kk], qa1[kk], qa2[kk], qa3[kk], b0, b1);
            }
        }

        // ---- scale (base-2 domain) + causal mask ----
        const bool needmask = (kt >= 2 * qt);
#pragma unroll
        for (int n = 0; n < 8; n++) {
#pragma unroll
            for (int j = 0; j < 4; j++) {
                float v = sacc[n][j] * scale2;
                if (needmask) {
                    int gk = kt * 64 + n * 8 + 2 * lr + (j & 1);
                    int gq = (j < 2) ? gq0 : gq1;
                    if (gk > gq) v += NEG_INF;
                }
                sacc[n][j] = v;
            }
        }

        // ---- online softmax (base 2): max only; sums via ones-MMA ----
        float mx0 = -1e30f, mx1 = -1e30f;
#pragma unroll
        for (int n = 0; n < 8; n++) {
            mx0 = fmaxf(mx0, fmaxf(sacc[n][0], sacc[n][1]));
            mx1 = fmaxf(mx1, fmaxf(sacc[n][2], sacc[n][3]));
        }
        mx0 = fmaxf(mx0, __shfl_xor_sync(0xffffffffu, mx0, 1));
        mx0 = fmaxf(mx0, __shfl_xor_sync(0xffffffffu, mx0, 2));
        mx1 = fmaxf(mx1, __shfl_xor_sync(0xffffffffu, mx1, 1));
        mx1 = fmaxf(mx1, __shfl_xor_sync(0xffffffffu, mx1, 2));
        float mn0 = fmaxf(m0, mx0);
        float mn1 = fmaxf(m1, mx1);
        float c0 = fexp2(m0 - mn0);
        float c1 = fexp2(m1 - mn1);
#pragma unroll
        for (int n = 0; n < 8; n++) {
            sacc[n][0] = fexp2(sacc[n][0] - mn0);
            sacc[n][1] = fexp2(sacc[n][1] - mn0);
            sacc[n][2] = fexp2(sacc[n][2] - mn1);
            sacc[n][3] = fexp2(sacc[n][3] - mn1);
        }
        m0 = mn0; m1 = mn1;
#pragma unroll
        for (int dt = 0; dt < 4; dt++) {
            oacc[dt][0] *= c0; oacc[dt][1] *= c0;
            oacc[dt][2] *= c1; oacc[dt][3] *= c1;
        }

        // ---- P -> fragment-major smem (raw fp32; MMA truncates) ----
        {
            float* Pw = Ps + wid * PWARP;
#pragma unroll
            for (int n = 0; n < 8; n++) {
#pragma unroll
                for (int j = 0; j < 4; j++) {
                    int cfull = 2 * lr + (j & 1);
                    int hc = cfull >> 2, lra = cfull & 3;
                    int hr = j >> 1;
                    int grp = (hr * 2 + hc) * 2 + (n >> 2);
                    Pw[grp * PGRP + (lq * 4 + lra) * 4 + (n & 3)] = sacc[n][j];
                }
            }
        }
        __syncwarp();

        // ---- P fragments (vectorized) ----
        uint32_t pa0[8], pa1[8], pa2[8], pa3[8];
        {
            const float* Pw = Ps + wid * PWARP;
#pragma unroll
            for (int q = 0; q < 2; q++) {
                float4 v00 = *(const float4*)(&Pw[((0 * 2 + 0) * 2 + q) * PGRP + lane * 4]);
                float4 v10 = *(const float4*)(&Pw[((1 * 2 + 0) * 2 + q) * PGRP + lane * 4]);
                float4 v01 = *(const float4*)(&Pw[((0 * 2 + 1) * 2 + q) * PGRP + lane * 4]);
                float4 v11 = *(const float4*)(&Pw[((1 * 2 + 1) * 2 + q) * PGRP + lane * 4]);
                pa0[q*4+0]=__float_as_uint(v00.x); pa0[q*4+1]=__float_as_uint(v00.y);
                pa0[q*4+2]=__float_as_uint(v00.z); pa0[q*4+3]=__float_as_uint(v00.w);
                pa1[q*4+0]=__float_as_uint(v10.x); pa1[q*4+1]=__float_as_uint(v10.y);
                pa1[q*4+2]=__float_as_uint(v10.z); pa1[q*4+3]=__float_as_uint(v10.w);
                pa2[q*4+0]=__float_as_uint(v01.x); pa2[q*4+1]=__float_as_uint(v01.y);
                pa2[q*4+2]=__float_as_uint(v01.z); pa2[q*4+3]=__float_as_uint(v01.w);
                pa3[q*4+0]=__float_as_uint(v11.x); pa3[q*4+1]=__float_as_uint(v11.y);
                pa3[q*4+2]=__float_as_uint(v11.z); pa3[q*4+3]=__float_as_uint(v11.w);
            }
        }

        // ---- row sums via ones-MMA (all output cols = row sum) ----
        {
            float ss[4] = {0.f, 0.f, 0.f, 0.f};
#pragma unroll
            for (int kk = 0; kk < 8; kk++)
                mma_tf32(ss, pa0[kk], pa1[kk], pa2[kk], pa3[kk], ONE, ONE);
            l0 = l0 * c0 + ss[0];
            l1 = l1 * c1 + ss[2];
        }

        // ---- O' += P lat : warp 16 x 32, k-dim 64 ----
#pragma unroll
        for (int dt = 0; dt < 4; dt++) {
#pragma unroll
            for (int kk = 0; kk < 8; kk++) {
                uint32_t b0 = __float_as_uint(Ltb[(dt * 8 + lq) * LT_STR + kk * 8 + lr]);
                uint32_t b1 = __float_as_uint(Ltb[(dt * 8 + lq) * LT_STR + kk * 8 + lr + 4]);
                mma_tf32(oacc[dt], pa0[kk], pa1[kk], pa2[kk], pa3[kk], b0, b1);
            }
        }
    }

    // ---- epilogue: O' [128 x 32] tf32-rounded ----
    float inv0 = 1.f / l0;
    float inv1 = 1.f / l1;
    const size_t obase = (size_t)(b * T) * 512 + h * LATENT;
#pragma unroll
    for (int dt = 0; dt < 4; dt++) {
        int col = dt * 8 + 2 * lr;
        *(float2*)(O + obase + (size_t)gq0 * 512 + col) =
            make_float2(f2tf(oacc[dt][0] * inv0), f2tf(oacc[dt][1] * inv0));
        *(float2*)(O + obase + (size_t)gq1 * 512 + col) =
            make_float2(f2tf(oacc[dt][2] * inv1), f2tf(oacc[dt][3] * inv1));
    }
}

// =====================================================================
// launch
// =====================================================================
extern "C" void kernel_launch(void* const* d_in, const int* in_sizes, int n_in,
                              void* d_out, int out_size) {
    const float* x    = (const float*)d_in[0];
    const float* W_kv = (const float*)d_in[1];
    const float* W_k  = (const float*)d_in[2];
    const float* W_v  = (const float*)d_in[3];
    const float* W_q  = (const float*)d_in[4];
    const float* W_o  = (const float*)d_in[5];
    float* out = (float*)d_out;

    const int BT = in_sizes[0] / D_MODEL;   // 8192
    const int T  = T_SEQ;
    const int B  = BT / T;

    float *lat, *latT, *Qf, *Of, *Xr, *Wqk, *Wvo;
    cudaGetSymbolAddress((void**)&lat,  g_lat);
    cudaGetSymbolAddress((void**)&latT, g_latT);
    cudaGetSymbolAddress((void**)&Qf,   g_Qp);
    cudaGetSymbolAddress((void**)&Of,   g_O);
    cudaGetSymbolAddress((void**)&Xr,   g_X);
    cudaGetSymbolAddress((void**)&Wqk,  g_Wqk);
    cudaGetSymbolAddress((void**)&Wvo,  g_Wvo);

    const int attn_smem = (2 * LS_SZ + 2 * LT_SZ + P_REGION) * (int)sizeof(float);
    cudaFuncSetAttribute(attn_kernel, cudaFuncAttributeMaxDynamicSharedMemorySize,
                         attn_smem);
    const int gemm_smem = 3 * GSTG * (int)sizeof(float);
    cudaFuncSetAttribute(gemm_tf32, cudaFuncAttributeMaxDynamicSharedMemorySize,
                         gemm_smem);

    // 0. pre-round x for the Q' GEMM
    {
        int n4 = BT * D_MODEL / 4;
        round_kernel<<<(n4 + 255) / 256, 256>>>(x, Xr, n4);
    }

    // 1. lat = x @ W_kv (exact fp32, tf32-rounded) + fused transpose
    lat_kernel<<<BT / 32, 256>>>(x, W_kv, lat, latT, T);

    // 2. folded weights
    wqk_kernel<<<dim3(N_HEADS, 16), 256>>>(W_q, W_k, Wqk);
    wvo_kernel<<<dim3(N_HEADS, 8), 256>>>(W_v, W_o, Wvo);

    // 3. Q' = x @ W_qk  [8192x1024x512]
    gemm_tf32<<<dim3(512 / 128, BT / 128), 256, gemm_smem>>>(Xr, Wqk, Qf, BT, 512, D_MODEL, 1);

    // 4. latent-space causal flash attention
    dim3 ga(T / 128, B * N_HEADS);
    attn_kernel<<<ga, 256, attn_smem>>>(Qf, lat, latT, Of, T);

    // 5. out = O' @ W_vo  [8192x512x1024]
    gemm_tf32<<<dim3(D_MODEL / 128, BT / 128), 256, gemm_smem>>>(Of, Wvo, out, BT, D_MODEL, 512, 0);
}